// round 7
// baseline (speedup 1.0000x reference)
#include <cuda_runtime.h>

// Problem constants
#define L_SEQ   8192
#define HIDN    1024
#define HEADS   16
#define HD      64
#define C3      3072
#define NSTATE  16
#define BATCH   2

// Scratch (allowed: __device__ global arrays)
__device__ float g_x1v[(size_t)BATCH * HIDN * L_SEQ];   // (B, HID, L) channel-major
__device__ float g_y  [(size_t)BATCH * HIDN * L_SEQ];   // (B, HID, L) y + D*x1v

// ---------------------------------------------------------------------------
// packed fp32x2 FMA (Blackwell)
union F2U { float2 f; unsigned long long u; };
__device__ __forceinline__ float2 ffma2(float2 a, float2 b, float2 c) {
    F2U A, B, C, D; A.f = a; B.f = b; C.f = c;
    asm("fma.rn.f32x2 %0, %1, %2, %3;" : "=l"(D.u) : "l"(A.u), "l"(B.u), "l"(C.u));
    return D.f;
}

// ---------------------------------------------------------------------------
// Kernel 1: bidirectional depthwise FIR (K=3) on x1/v channels, produce x1v.
// z[t] = w0*(u[t-2]+u[t+2]) + w1*(u[t-1]+u[t+1]) + 2*w2*u[t]
// Block: (t-tile of 64, head, b). 256 threads.
__global__ __launch_bounds__(256) void k_fir_x1v(const float* __restrict__ u,
                                                 const float* __restrict__ w) {
    const int t0   = blockIdx.x * 64;
    const int head = blockIdx.y;
    const int b    = blockIdx.z;
    const int tid  = threadIdx.x;

    __shared__ float su[68 * 129];   // 68 time rows x 128 channels (pad 129)
    __shared__ float sw[128 * 3];

    const int chbase = head * 192 + 64;   // x1 channels [0,64), v channels [64,128)

    for (int i = tid; i < 384; i += 256) sw[i] = w[chbase * 3 + i];

    for (int s = tid; s < 68 * 32; s += 256) {
        const int row = s >> 5, c4 = s & 31;
        const int t = t0 - 2 + row;
        float4 v = make_float4(0.f, 0.f, 0.f, 0.f);
        if (t >= 0 && t < L_SEQ)
            v = *(const float4*)(u + (size_t)(b * L_SEQ + t) * C3 + chbase + c4 * 4);
        float* dst = su + row * 129 + c4 * 4;
        dst[0] = v.x; dst[1] = v.y; dst[2] = v.z; dst[3] = v.w;
    }
    __syncthreads();

    const int tl = tid & 63;
    const int dq = tid >> 6;
#pragma unroll 4
    for (int dd = 0; dd < 64; dd += 4) {
        const int d = dd + dq;
        const float* pa = su + tl * 129 + d;        // x1
        const float* pb = pa + 64;                  // v
        const float wa0 = sw[d * 3], wa1 = sw[d * 3 + 1], wa2 = sw[d * 3 + 2];
        const float wb0 = sw[(64 + d) * 3], wb1 = sw[(64 + d) * 3 + 1], wb2 = sw[(64 + d) * 3 + 2];
        const float z1 = wa0 * (pa[0] + pa[4 * 129]) + wa1 * (pa[129] + pa[3 * 129]) + 2.f * wa2 * pa[2 * 129];
        const float z2 = wb0 * (pb[0] + pb[4 * 129]) + wb1 * (pb[129] + pb[3 * 129]) + 2.f * wb2 * pb[2 * 129];
        g_x1v[(size_t)(b * HIDN + head * HD + d) * L_SEQ + t0 + tl] = z1 * z2;
    }
}

// ---------------------------------------------------------------------------
// Kernel 2: bidirectional 16-state SSM scan per (b, channel) row.
// y[t] = sum_s r_s * (S_s[t] + T_s[t]) + D[c]*x[t]
//   S_s[t] = p_s S_s[t-1] + x[t]   (forward)
//   T_s[t] = p_s T_s[t+1] + x[t]   (backward)
// 256 threads, chunk M=32, chunked 2-pass scan + Kogge-Stone carry combine.
#define PADN 8448         // 8192 + 256 pad floats
#define SCST 17           // carry row stride (floats)

__global__ __launch_bounds__(256) void k_scan(const float* __restrict__ lp,
                                              const float* __restrict__ res,
                                              const float* __restrict__ Dv) {
    extern __shared__ float sm[];
    float* xs = sm;                 // padded x1v row  (8448)
    float* ys = sm + PADN;          // padded y row    (8448)
    float* sc = sm + 2 * PADN;      // carries 256*17  (4352)

    const int tid = threadIdx.x;        // chunk id
    const int bc  = blockIdx.x;         // b*HID + c
    const float* xrow = g_x1v + (size_t)bc * L_SEQ;
    float*       yrow = g_y   + (size_t)bc * L_SEQ;
    const float dC = Dv[bc & (HIDN - 1)];

    float2 p2[8], r2[8];
#pragma unroll
    for (int k = 0; k < 8; k++) {
        p2[k] = make_float2(expf(lp[2 * k]), expf(lp[2 * k + 1]));
        r2[k] = make_float2(res[2 * k], res[2 * k + 1]);
    }

    // load x1v into padded smem (pad = t>>5 -> conflict-free chunk access)
    for (int t = tid; t < L_SEQ; t += 256) xs[t + (t >> 5)] = xrow[t];
    __syncthreads();

#pragma unroll
    for (int dir = 0; dir < 2; dir++) {
        // scan position s = tid*32 + i ; t = dir ? 8191-s : s
        // padded address is linear in i for both directions:
        const int base = dir ? (8446 - 33 * tid) : (33 * tid);
        const int stp  = dir ? -1 : 1;

        float2 S[8];
#pragma unroll
        for (int k = 0; k < 8; k++) S[k] = make_float2(0.f, 0.f);

        // pass 1: local chunk end-states (zero init)
#pragma unroll 4
        for (int i = 0; i < 32; i++) {
            const float x = xs[base + stp * i];
            const float2 fx = make_float2(x, x);
#pragma unroll
            for (int k = 0; k < 8; k++) S[k] = ffma2(p2[k], S[k], fx);
        }

        // chunk decay q = p^32 (5 squarings)
        float2 q2[8];
#pragma unroll
        for (int k = 0; k < 8; k++) {
            float2 q = p2[k];
#pragma unroll
            for (int sq = 0; sq < 5; sq++) { q.x *= q.x; q.y *= q.y; }
            q2[k] = q;
        }

        // Kogge-Stone inclusive scan over 256 chunk carries
        for (int d = 1; d < 256; d <<= 1) {
#pragma unroll
            for (int k = 0; k < 8; k++) {
                sc[tid * SCST + 2 * k]     = S[k].x;
                sc[tid * SCST + 2 * k + 1] = S[k].y;
            }
            __syncthreads();
            float2 P[8];
            const bool act = (tid >= d);
            if (act) {
#pragma unroll
                for (int k = 0; k < 8; k++)
                    P[k] = make_float2(sc[(tid - d) * SCST + 2 * k],
                                       sc[(tid - d) * SCST + 2 * k + 1]);
            }
            __syncthreads();
            if (act) {
#pragma unroll
                for (int k = 0; k < 8; k++) S[k] = ffma2(q2[k], P[k], S[k]);
            }
#pragma unroll
            for (int k = 0; k < 8; k++) { q2[k].x *= q2[k].x; q2[k].y *= q2[k].y; }
        }

        // exclusive carry-in = inclusive state of chunk tid-1
#pragma unroll
        for (int k = 0; k < 8; k++) {
            sc[tid * SCST + 2 * k]     = S[k].x;
            sc[tid * SCST + 2 * k + 1] = S[k].y;
        }
        __syncthreads();
        if (tid > 0) {
#pragma unroll
            for (int k = 0; k < 8; k++)
                S[k] = make_float2(sc[(tid - 1) * SCST + 2 * k],
                                   sc[(tid - 1) * SCST + 2 * k + 1]);
        } else {
#pragma unroll
            for (int k = 0; k < 8; k++) S[k] = make_float2(0.f, 0.f);
        }
        __syncthreads();

        // pass 2: re-scan with carry-in, emit y contributions
#pragma unroll 4
        for (int i = 0; i < 32; i++) {
            const int a = base + stp * i;
            const float x = xs[a];
            const float2 fx = make_float2(x, x);
#pragma unroll
            for (int k = 0; k < 8; k++) S[k] = ffma2(p2[k], S[k], fx);
            float2 aA = make_float2(0.f, 0.f), aB = make_float2(0.f, 0.f);
            aA = ffma2(r2[0], S[0], aA);  aB = ffma2(r2[1], S[1], aB);
            aA = ffma2(r2[2], S[2], aA);  aB = ffma2(r2[3], S[3], aB);
            aA = ffma2(r2[4], S[4], aA);  aB = ffma2(r2[5], S[5], aB);
            aA = ffma2(r2[6], S[6], aA);  aB = ffma2(r2[7], S[7], aB);
            const float y = (aA.x + aB.x) + (aA.y + aB.y);
            if (dir == 0) ys[a] = y;
            else          ys[a] = ys[a] + y + dC * x;
        }
        // (no explicit sync needed here: the next direction's Kogge-Stone
        //  barriers order ys writes before any cross-thread ys reads)
    }
    __syncthreads();

    // coalesced stream-out
    for (int t = tid; t < L_SEQ; t += 256) yrow[t] = ys[t + (t >> 5)];
}

// ---------------------------------------------------------------------------
// Kernel 3: gate FIR (x2) + multiply + transpose to (B, L, HID) output.
__global__ __launch_bounds__(256) void k_gate_out(const float* __restrict__ u,
                                                  const float* __restrict__ w,
                                                  float* __restrict__ out) {
    const int t0   = blockIdx.x * 64;
    const int head = blockIdx.y;
    const int b    = blockIdx.z;
    const int tid  = threadIdx.x;

    __shared__ float su[68 * 65];   // x2-part u tile: 68 time rows x 64 ch (pad 65)
    __shared__ float sy[64 * 65];   // y tile: 64 ch x 64 t (pad 65)
    __shared__ float sw[64 * 3];

    const int chbase = head * 192;  // x2 channels

    for (int i = tid; i < 192; i += 256) sw[i] = w[chbase * 3 + i];

    for (int s = tid; s < 68 * 16; s += 256) {
        const int row = s >> 4, c4 = s & 15;
        const int t = t0 - 2 + row;
        float4 v = make_float4(0.f, 0.f, 0.f, 0.f);
        if (t >= 0 && t < L_SEQ)
            v = *(const float4*)(u + (size_t)(b * L_SEQ + t) * C3 + chbase + c4 * 4);
        float* dst = su + row * 65 + c4 * 4;
        dst[0] = v.x; dst[1] = v.y; dst[2] = v.z; dst[3] = v.w;
    }
    for (int s = tid; s < 64 * 16; s += 256) {
        const int d = s >> 4, c4 = s & 15;
        const float4 v = *(const float4*)(g_y + (size_t)(b * HIDN + head * HD + d) * L_SEQ + t0 + c4 * 4);
        float* dst = sy + d * 65 + c4 * 4;
        dst[0] = v.x; dst[1] = v.y; dst[2] = v.z; dst[3] = v.w;
    }
    __syncthreads();

    const int d  = tid & 63;
    const int tq = tid >> 6;
    const float w0 = sw[d * 3], w1 = sw[d * 3 + 1], w2 = sw[d * 3 + 2];
#pragma unroll 4
    for (int tt = 0; tt < 64; tt += 4) {
        const int tl = tq + tt;
        const float* p = su + tl * 65 + d;
        const float x2 = w0 * (p[0] + p[4 * 65]) + w1 * (p[65] + p[3 * 65]) + 2.f * w2 * p[2 * 65];
        out[(size_t)(b * L_SEQ + t0 + tl) * HIDN + head * HD + d] = sy[d * 65 + tl] * x2;
    }
}

// ---------------------------------------------------------------------------
extern "C" void kernel_launch(void* const* d_in, const int* in_sizes, int n_in,
                              void* d_out, int out_size) {
    const float* u   = (const float*)d_in[0];
    const float* w   = (const float*)d_in[1];
    const float* lp  = (const float*)d_in[2];
    const float* res = (const float*)d_in[3];
    const float* D   = (const float*)d_in[4];
    float* out = (float*)d_out;

    const size_t SH = (size_t)(2 * PADN + 256 * SCST) * sizeof(float);  // 84992 B
    cudaFuncSetAttribute(k_scan, cudaFuncAttributeMaxDynamicSharedMemorySize, (int)SH);

    dim3 blk(256);
    k_fir_x1v<<<dim3(L_SEQ / 64, HEADS, BATCH), blk>>>(u, w);
    k_scan<<<dim3(BATCH * HIDN), blk, SH>>>(lp, res, D);
    k_gate_out<<<dim3(L_SEQ / 64, HEADS, BATCH), blk>>>(u, w, out);
}

// round 9
// speedup vs baseline: 1.0433x; 1.0433x over previous
#include <cuda_runtime.h>

// Problem constants
#define L_SEQ   8192
#define HIDN    1024
#define HEADS   16
#define HD      64
#define C3      3072
#define NSTATE  16
#define BATCH   2

// Scratch (allowed: __device__ global arrays)
__device__ float g_x1v[(size_t)BATCH * HIDN * L_SEQ];   // (B, HID, L) channel-major
__device__ float g_y  [(size_t)BATCH * HIDN * L_SEQ];   // (B, HID, L) y + D*x1v

// ---------------------------------------------------------------------------
// packed fp32x2 FMA (Blackwell)
union F2U { float2 f; unsigned long long u; };
__device__ __forceinline__ float2 ffma2(float2 a, float2 b, float2 c) {
    F2U A, B, C, D; A.f = a; B.f = b; C.f = c;
    asm("fma.rn.f32x2 %0, %1, %2, %3;" : "=l"(D.u) : "l"(A.u), "l"(B.u), "l"(C.u));
    return D.f;
}

// ---------------------------------------------------------------------------
// Kernel 1: bidirectional depthwise FIR (K=3) on x1/v channels, produce x1v.
// z[t] = w0*(u[t-2]+u[t+2]) + w1*(u[t-1]+u[t+1]) + 2*w2*u[t]
// Rolling-window version: thread = (channel d, t-quarter q), 1 LDS per
// channel per new t instead of 10 LDS per output.
__global__ __launch_bounds__(256) void k_fir_x1v(const float* __restrict__ u,
                                                 const float* __restrict__ w) {
    const int t0   = blockIdx.x * 64;
    const int head = blockIdx.y;
    const int b    = blockIdx.z;
    const int tid  = threadIdx.x;

    __shared__ float su[68 * 132];   // 68 time rows x 128 ch (pad->132, STS.128 OK)
    __shared__ float sw[128 * 3];

    const int chbase = head * 192 + 64;   // x1 ch [0,64), v ch [64,128)

    for (int i = tid; i < 384; i += 256) sw[i] = w[chbase * 3 + i];

    for (int s = tid; s < 68 * 32; s += 256) {
        const int row = s >> 5, c4 = s & 31;
        const int t = t0 - 2 + row;
        float4 v = make_float4(0.f, 0.f, 0.f, 0.f);
        if (t >= 0 && t < L_SEQ)
            v = *(const float4*)(u + (size_t)(b * L_SEQ + t) * C3 + chbase + c4 * 4);
        *(float4*)(su + row * 132 + c4 * 4) = v;
    }
    __syncthreads();

    const int d = tid & 63;            // channel within head
    const int q = tid >> 6;            // t-quarter: t in [q*16, q*16+16)

    const float wa0 = sw[d * 3], wa1 = sw[d * 3 + 1], wa2s = 2.f * sw[d * 3 + 2];
    const float wb0 = sw[(64 + d) * 3], wb1 = sw[(64 + d) * 3 + 1],
                wb2s = 2.f * sw[(64 + d) * 3 + 2];

    // output tl uses su rows tl..tl+4 (row r <-> time t0-2+r)
    const float* pa = su + (q * 16) * 132 + d;        // x1 column
    const float* pb = pa + 64;                        // v column
    float a0 = pa[0], a1 = pa[132], a2 = pa[264], a3 = pa[396];
    float b0 = pb[0], b1 = pb[132], b2 = pb[264], b3 = pb[396];

    float* orow = g_x1v + (size_t)(b * HIDN + head * HD + d) * L_SEQ + t0 + q * 16;

    float4 buf;
#pragma unroll
    for (int k = 0; k < 16; k++) {
        const float a4 = pa[(k + 4) * 132];           // 1 LDS, lanes over d: conflict-free
        const float b4 = pb[(k + 4) * 132];
        const float z1 = wa0 * (a0 + a4) + wa1 * (a1 + a3) + wa2s * a2;
        const float z2 = wb0 * (b0 + b4) + wb1 * (b1 + b3) + wb2s * b2;
        const float z = z1 * z2;
        if ((k & 3) == 0) buf.x = z;
        else if ((k & 3) == 1) buf.y = z;
        else if ((k & 3) == 2) buf.z = z;
        else { buf.w = z; *(float4*)(orow + (k & ~3)) = buf; }
        a0 = a1; a1 = a2; a2 = a3; a3 = a4;
        b0 = b1; b1 = b2; b2 = b3; b3 = b4;
    }
}

// ---------------------------------------------------------------------------
// Kernel 2: bidirectional 16-state SSM scan per (b, channel) row. (unchanged)
#define PADN 8448         // 8192 + 256 pad floats
#define SCST 17           // carry row stride (floats)

__global__ __launch_bounds__(256) void k_scan(const float* __restrict__ lp,
                                              const float* __restrict__ res,
                                              const float* __restrict__ Dv) {
    extern __shared__ float sm[];
    float* xs = sm;                 // padded x1v row  (8448)
    float* ys = sm + PADN;          // padded y row    (8448)
    float* sc = sm + 2 * PADN;      // carries 256*17  (4352)

    const int tid = threadIdx.x;        // chunk id
    const int bc  = blockIdx.x;         // b*HID + c
    const float* xrow = g_x1v + (size_t)bc * L_SEQ;
    float*       yrow = g_y   + (size_t)bc * L_SEQ;
    const float dC = Dv[bc & (HIDN - 1)];

    float2 p2[8], r2[8];
#pragma unroll
    for (int k = 0; k < 8; k++) {
        p2[k] = make_float2(expf(lp[2 * k]), expf(lp[2 * k + 1]));
        r2[k] = make_float2(res[2 * k], res[2 * k + 1]);
    }

    for (int t = tid; t < L_SEQ; t += 256) xs[t + (t >> 5)] = xrow[t];
    __syncthreads();

#pragma unroll
    for (int dir = 0; dir < 2; dir++) {
        const int base = dir ? (8446 - 33 * tid) : (33 * tid);
        const int stp  = dir ? -1 : 1;

        float2 S[8];
#pragma unroll
        for (int k = 0; k < 8; k++) S[k] = make_float2(0.f, 0.f);

#pragma unroll 4
        for (int i = 0; i < 32; i++) {
            const float x = xs[base + stp * i];
            const float2 fx = make_float2(x, x);
#pragma unroll
            for (int k = 0; k < 8; k++) S[k] = ffma2(p2[k], S[k], fx);
        }

        float2 q2[8];
#pragma unroll
        for (int k = 0; k < 8; k++) {
            float2 q = p2[k];
#pragma unroll
            for (int sq = 0; sq < 5; sq++) { q.x *= q.x; q.y *= q.y; }
            q2[k] = q;
        }

        for (int d = 1; d < 256; d <<= 1) {
#pragma unroll
            for (int k = 0; k < 8; k++) {
                sc[tid * SCST + 2 * k]     = S[k].x;
                sc[tid * SCST + 2 * k + 1] = S[k].y;
            }
            __syncthreads();
            float2 P[8];
            const bool act = (tid >= d);
            if (act) {
#pragma unroll
                for (int k = 0; k < 8; k++)
                    P[k] = make_float2(sc[(tid - d) * SCST + 2 * k],
                                       sc[(tid - d) * SCST + 2 * k + 1]);
            }
            __syncthreads();
            if (act) {
#pragma unroll
                for (int k = 0; k < 8; k++) S[k] = ffma2(q2[k], P[k], S[k]);
            }
#pragma unroll
            for (int k = 0; k < 8; k++) { q2[k].x *= q2[k].x; q2[k].y *= q2[k].y; }
        }

#pragma unroll
        for (int k = 0; k < 8; k++) {
            sc[tid * SCST + 2 * k]     = S[k].x;
            sc[tid * SCST + 2 * k + 1] = S[k].y;
        }
        __syncthreads();
        if (tid > 0) {
#pragma unroll
            for (int k = 0; k < 8; k++)
                S[k] = make_float2(sc[(tid - 1) * SCST + 2 * k],
                                   sc[(tid - 1) * SCST + 2 * k + 1]);
        } else {
#pragma unroll
            for (int k = 0; k < 8; k++) S[k] = make_float2(0.f, 0.f);
        }
        __syncthreads();

#pragma unroll 4
        for (int i = 0; i < 32; i++) {
            const int a = base + stp * i;
            const float x = xs[a];
            const float2 fx = make_float2(x, x);
#pragma unroll
            for (int k = 0; k < 8; k++) S[k] = ffma2(p2[k], S[k], fx);
            float2 aA = make_float2(0.f, 0.f), aB = make_float2(0.f, 0.f);
            aA = ffma2(r2[0], S[0], aA);  aB = ffma2(r2[1], S[1], aB);
            aA = ffma2(r2[2], S[2], aA);  aB = ffma2(r2[3], S[3], aB);
            aA = ffma2(r2[4], S[4], aA);  aB = ffma2(r2[5], S[5], aB);
            aA = ffma2(r2[6], S[6], aA);  aB = ffma2(r2[7], S[7], aB);
            const float y = (aA.x + aB.x) + (aA.y + aB.y);
            if (dir == 0) ys[a] = y;
            else          ys[a] = ys[a] + y + dC * x;
        }
    }
    __syncthreads();

    for (int t = tid; t < L_SEQ; t += 256) yrow[t] = ys[t + (t >> 5)];
}

// ---------------------------------------------------------------------------
// Kernel 3: gate FIR (x2) + multiply + transpose to (B, L, HID) output.
// Rolling-window version: 2 LDS per output instead of 6; STG stays 128B
// coalesced (lanes over d, out has channels innermost).
__global__ __launch_bounds__(256) void k_gate_out(const float* __restrict__ u,
                                                  const float* __restrict__ w,
                                                  float* __restrict__ out) {
    const int t0   = blockIdx.x * 64;
    const int head = blockIdx.y;
    const int b    = blockIdx.z;
    const int tid  = threadIdx.x;

    __shared__ float su[68 * 68];   // x2 u tile: 68 t rows x 64 ch (pad->68)
    __shared__ float sy[64 * 65];   // y tile: 64 ch x 64 t (pad 65, odd stride)
    __shared__ float sw[64 * 3];

    const int chbase = head * 192;  // x2 channels

    for (int i = tid; i < 192; i += 256) sw[i] = w[chbase * 3 + i];

    for (int s = tid; s < 68 * 16; s += 256) {
        const int row = s >> 4, c4 = s & 15;
        const int t = t0 - 2 + row;
        float4 v = make_float4(0.f, 0.f, 0.f, 0.f);
        if (t >= 0 && t < L_SEQ)
            v = *(const float4*)(u + (size_t)(b * L_SEQ + t) * C3 + chbase + c4 * 4);
        *(float4*)(su + row * 68 + c4 * 4) = v;
    }
    for (int s = tid; s < 64 * 16; s += 256) {
        const int dch = s >> 4, c4 = s & 15;
        const float4 v = *(const float4*)(g_y + (size_t)(b * HIDN + head * HD + dch) * L_SEQ + t0 + c4 * 4);
        float* dst = sy + dch * 65 + c4 * 4;
        dst[0] = v.x; dst[1] = v.y; dst[2] = v.z; dst[3] = v.w;
    }
    __syncthreads();

    const int d = tid & 63;
    const int q = tid >> 6;
    const float w0 = sw[d * 3], w1 = sw[d * 3 + 1], w2s = 2.f * sw[d * 3 + 2];

    const float* p  = su + (q * 16) * 68 + d;   // lanes over d: conflict-free
    const float* py = sy + d * 65 + q * 16;     // stride 65 odd: conflict-free

    float a0 = p[0], a1 = p[68], a2 = p[136], a3 = p[204];
    float* orow = out + (size_t)(b * L_SEQ + t0 + q * 16) * HIDN + head * HD + d;

#pragma unroll
    for (int k = 0; k < 16; k++) {
        const float a4 = p[(k + 4) * 68];
        const float x2 = w0 * (a0 + a4) + w1 * (a1 + a3) + w2s * a2;
        orow[(size_t)k * HIDN] = py[k] * x2;     // 128B coalesced per k
        a0 = a1; a1 = a2; a2 = a3; a3 = a4;
    }
}

// ---------------------------------------------------------------------------
extern "C" void kernel_launch(void* const* d_in, const int* in_sizes, int n_in,
                              void* d_out, int out_size) {
    const float* u   = (const float*)d_in[0];
    const float* w   = (const float*)d_in[1];
    const float* lp  = (const float*)d_in[2];
    const float* res = (const float*)d_in[3];
    const float* D   = (const float*)d_in[4];
    float* out = (float*)d_out;

    const size_t SH = (size_t)(2 * PADN + 256 * SCST) * sizeof(float);  // 84992 B
    cudaFuncSetAttribute(k_scan, cudaFuncAttributeMaxDynamicSharedMemorySize, (int)SH);

    dim3 blk(256);
    k_fir_x1v<<<dim3(L_SEQ / 64, HEADS, BATCH), blk>>>(u, w);
    k_scan<<<dim3(BATCH * HIDN), blk, SH>>>(lp, res, D);
    k_gate_out<<<dim3(L_SEQ / 64, HEADS, BATCH), blk>>>(u, w, out);
}

// round 12
// speedup vs baseline: 1.1298x; 1.0829x over previous
#include <cuda_runtime.h>

// Problem constants
#define L_SEQ   8192
#define HIDN    1024
#define HEADS   16
#define HD      64
#define C3      3072
#define NSTATE  16
#define BATCH   2

// Scratch (allowed: __device__ global arrays)
__device__ float g_x1v[(size_t)BATCH * HIDN * L_SEQ];   // (B, HID, L) channel-major
__device__ float g_y  [(size_t)BATCH * HIDN * L_SEQ];   // (B, HID, L) y + D*x1v

// ---------------------------------------------------------------------------
// packed fp32x2 FMA (Blackwell)
union F2U { float2 f; unsigned long long u; };
__device__ __forceinline__ float2 ffma2(float2 a, float2 b, float2 c) {
    F2U A, B, C, D; A.f = a; B.f = b; C.f = c;
    asm("fma.rn.f32x2 %0, %1, %2, %3;" : "=l"(D.u) : "l"(A.u), "l"(B.u), "l"(C.u));
    return D.f;
}

// ---------------------------------------------------------------------------
// Kernel 1: bidirectional depthwise FIR (K=3) on x1/v channels, produce x1v.
// z[t] = w0*(u[t-2]+u[t+2]) + w1*(u[t-1]+u[t+1]) + 2*w2*u[t]
// Rolling window (1 LDS/channel/t) + smem staging so the g_x1v store is
// fully coalesced (lanes over t) instead of 32-line scattered STG.128.
__global__ __launch_bounds__(256) void k_fir_x1v(const float* __restrict__ u,
                                                 const float* __restrict__ w) {
    const int t0   = blockIdx.x * 64;
    const int head = blockIdx.y;
    const int b    = blockIdx.z;
    const int tid  = threadIdx.x;

    __shared__ float su[68 * 132];   // 68 time rows x 128 ch (pad->132)
    __shared__ float st[64 * 65];    // staging: 64 ch x 64 t (pad 65)
    __shared__ float sw[128 * 3];

    const int chbase = head * 192 + 64;   // x1 ch [0,64), v ch [64,128)

    for (int i = tid; i < 384; i += 256) sw[i] = w[chbase * 3 + i];

    for (int s = tid; s < 68 * 32; s += 256) {
        const int row = s >> 5, c4 = s & 31;
        const int t = t0 - 2 + row;
        float4 v = make_float4(0.f, 0.f, 0.f, 0.f);
        if (t >= 0 && t < L_SEQ)
            v = *(const float4*)(u + (size_t)(b * L_SEQ + t) * C3 + chbase + c4 * 4);
        *(float4*)(su + row * 132 + c4 * 4) = v;
    }
    __syncthreads();

    const int d = tid & 63;            // channel within head
    const int q = tid >> 6;            // t-quarter: t in [q*16, q*16+16)

    const float wa0 = sw[d * 3], wa1 = sw[d * 3 + 1], wa2s = 2.f * sw[d * 3 + 2];
    const float wb0 = sw[(64 + d) * 3], wb1 = sw[(64 + d) * 3 + 1],
                wb2s = 2.f * sw[(64 + d) * 3 + 2];

    const float* pa = su + (q * 16) * 132 + d;        // x1 column
    const float* pb = pa + 64;                        // v column
    float a0 = pa[0], a1 = pa[132], a2 = pa[264], a3 = pa[396];
    float b0 = pb[0], b1 = pb[132], b2 = pb[264], b3 = pb[396];

    float* srow = st + d * 65 + q * 16;

#pragma unroll
    for (int k = 0; k < 16; k++) {
        const float a4 = pa[(k + 4) * 132];
        const float b4 = pb[(k + 4) * 132];
        const float z1 = wa0 * (a0 + a4) + wa1 * (a1 + a3) + wa2s * a2;
        const float z2 = wb0 * (b0 + b4) + wb1 * (b1 + b3) + wb2s * b2;
        srow[k] = z1 * z2;            // lanes over d, stride 65: conflict-free
        a0 = a1; a1 = a2; a2 = a3; a3 = a4;
        b0 = b1; b1 = b2; b2 = b3; b3 = b4;
    }
    __syncthreads();

    // coalesced store: s -> (ch, 16B chunk of t)
    for (int s = tid; s < 64 * 16; s += 256) {
        const int ch = s >> 4, c4 = s & 15;
        const float* p = st + ch * 65 + c4 * 4;
        float4 v = make_float4(p[0], p[1], p[2], p[3]);
        *(float4*)(g_x1v + (size_t)(b * HIDN + head * HD + ch) * L_SEQ + t0 + c4 * 4) = v;
    }
}

// ---------------------------------------------------------------------------
// Kernel 2: bidirectional 16-state SSM scan per (b, channel) row.
// Combined-direction version: thread tid owns t in [tid*32, tid*32+32) for
// BOTH directions (bwd chunk index = 255-tid), so one set of Kogge-Stone
// barrier rounds serves both scans. Carry buffer aliases the y buffer.
#define PADN 8448         // 8192 + 256 pad floats
#define SCST 33           // carry row stride (floats): 32 payload + 1 pad

__global__ __launch_bounds__(256, 3) void k_scan(const float* __restrict__ lp,
                                                 const float* __restrict__ res,
                                                 const float* __restrict__ Dv) {
    extern __shared__ float sm[];
    float* xs = sm;                 // padded x1v row  (8448)
    float* ys = sm + PADN;          // padded y row    (8448)  [aliases carries]
    float* sc = ys;                 // carries 256*33 = 8448 (used before ys writes)

    const int tid = threadIdx.x;        // chunk id (fwd); bwd chunk = 255-tid
    const int bc  = blockIdx.x;         // b*HID + c
    const float* xrow = g_x1v + (size_t)bc * L_SEQ;
    float*       yrow = g_y   + (size_t)bc * L_SEQ;
    const float dC = Dv[bc & (HIDN - 1)];

    float2 p2[8], r2[8];
#pragma unroll
    for (int k = 0; k < 8; k++) {
        p2[k] = make_float2(expf(lp[2 * k]), expf(lp[2 * k + 1]));
        r2[k] = make_float2(res[2 * k], res[2 * k + 1]);
    }

    // vectorized load into padded smem (pad = t>>5)
    for (int s = tid; s < L_SEQ / 4; s += 256) {
        const float4 v = *(const float4*)(xrow + s * 4);
        const int t = s * 4;
        float* dst = xs + t + (t >> 5);
        dst[0] = v.x; dst[1] = v.y; dst[2] = v.z; dst[3] = v.w;
    }
    __syncthreads();

    const int base = 33 * tid;          // thread's padded t-range start

    // ---- pass 1: local chunk scans, both directions in one loop ----
    float2 Sf[8], Sb[8];
#pragma unroll
    for (int k = 0; k < 8; k++) { Sf[k] = make_float2(0.f, 0.f); Sb[k] = Sf[k]; }

#pragma unroll 4
    for (int i = 0; i < 32; i++) {
        const float xf = xs[base + i];
        const float xb = xs[base + 31 - i];
        const float2 f = make_float2(xf, xf);
        const float2 g = make_float2(xb, xb);
#pragma unroll
        for (int k = 0; k < 8; k++) {
            Sf[k] = ffma2(p2[k], Sf[k], f);
            Sb[k] = ffma2(p2[k], Sb[k], g);
        }
    }

    // chunk decay q = p^32 (shared by both directions)
    float2 q2[8];
#pragma unroll
    for (int k = 0; k < 8; k++) {
        float2 q = p2[k];
#pragma unroll
        for (int sq = 0; sq < 5; sq++) { q.x *= q.x; q.y *= q.y; }
        q2[k] = q;
    }

    // ---- Kogge-Stone over 256 chunk carries, both dirs per round ----
    for (int d = 1; d < 256; d <<= 1) {
#pragma unroll
        for (int k = 0; k < 8; k++) {
            sc[tid * SCST + 2 * k]          = Sf[k].x;
            sc[tid * SCST + 2 * k + 1]      = Sf[k].y;
            sc[tid * SCST + 16 + 2 * k]     = Sb[k].x;
            sc[tid * SCST + 16 + 2 * k + 1] = Sb[k].y;
        }
        __syncthreads();
        const bool af = (tid >= d);
        const bool ab = (tid + d < 256);
        float2 Pf[8], Pb[8];
        if (af) {
#pragma unroll
            for (int k = 0; k < 8; k++)
                Pf[k] = make_float2(sc[(tid - d) * SCST + 2 * k],
                                    sc[(tid - d) * SCST + 2 * k + 1]);
        }
        if (ab) {
#pragma unroll
            for (int k = 0; k < 8; k++)
                Pb[k] = make_float2(sc[(tid + d) * SCST + 16 + 2 * k],
                                    sc[(tid + d) * SCST + 16 + 2 * k + 1]);
        }
        __syncthreads();
        if (af) {
#pragma unroll
            for (int k = 0; k < 8; k++) Sf[k] = ffma2(q2[k], Pf[k], Sf[k]);
        }
        if (ab) {
#pragma unroll
            for (int k = 0; k < 8; k++) Sb[k] = ffma2(q2[k], Pb[k], Sb[k]);
        }
#pragma unroll
        for (int k = 0; k < 8; k++) { q2[k].x *= q2[k].x; q2[k].y *= q2[k].y; }
    }

    // ---- exclusive carry-in: fwd from tid-1, bwd from tid+1 ----
#pragma unroll
    for (int k = 0; k < 8; k++) {
        sc[tid * SCST + 2 * k]          = Sf[k].x;
        sc[tid * SCST + 2 * k + 1]      = Sf[k].y;
        sc[tid * SCST + 16 + 2 * k]     = Sb[k].x;
        sc[tid * SCST + 16 + 2 * k + 1] = Sb[k].y;
    }
    __syncthreads();
    if (tid > 0) {
#pragma unroll
        for (int k = 0; k < 8; k++)
            Sf[k] = make_float2(sc[(tid - 1) * SCST + 2 * k],
                                sc[(tid - 1) * SCST + 2 * k + 1]);
    } else {
#pragma unroll
        for (int k = 0; k < 8; k++) Sf[k] = make_float2(0.f, 0.f);
    }
    if (tid < 255) {
#pragma unroll
        for (int k = 0; k < 8; k++)
            Sb[k] = make_float2(sc[(tid + 1) * SCST + 16 + 2 * k],
                                sc[(tid + 1) * SCST + 16 + 2 * k + 1]);
    } else {
#pragma unroll
        for (int k = 0; k < 8; k++) Sb[k] = make_float2(0.f, 0.f);
    }
    __syncthreads();   // all carry reads done before ys (same memory) is written

    // ---- pass 2A: forward finish, write yf ----
#pragma unroll 4
    for (int i = 0; i < 32; i++) {
        const int a = base + i;
        const float x = xs[a];
        const float2 fx = make_float2(x, x);
#pragma unroll
        for (int k = 0; k < 8; k++) Sf[k] = ffma2(p2[k], Sf[k], fx);
        float2 aA = make_float2(0.f, 0.f), aB = make_float2(0.f, 0.f);
        aA = ffma2(r2[0], Sf[0], aA);  aB = ffma2(r2[1], Sf[1], aB);
        aA = ffma2(r2[2], Sf[2], aA);  aB = ffma2(r2[3], Sf[3], aB);
        aA = ffma2(r2[4], Sf[4], aA);  aB = ffma2(r2[5], Sf[5], aB);
        aA = ffma2(r2[6], Sf[6], aA);  aB = ffma2(r2[7], Sf[7], aB);
        ys[a] = (aA.x + aB.x) + (aA.y + aB.y);
    }

    // ---- pass 2B: backward finish, accumulate (same-thread addresses) ----
#pragma unroll 4
    for (int i = 0; i < 32; i++) {
        const int a = base + 31 - i;
        const float x = xs[a];
        const float2 fx = make_float2(x, x);
#pragma unroll
        for (int k = 0; k < 8; k++) Sb[k] = ffma2(p2[k], Sb[k], fx);
        float2 aA = make_float2(0.f, 0.f), aB = make_float2(0.f, 0.f);
        aA = ffma2(r2[0], Sb[0], aA);  aB = ffma2(r2[1], Sb[1], aB);
        aA = ffma2(r2[2], Sb[2], aA);  aB = ffma2(r2[3], Sb[3], aB);
        aA = ffma2(r2[4], Sb[4], aA);  aB = ffma2(r2[5], Sb[5], aB);
        aA = ffma2(r2[6], Sb[6], aA);  aB = ffma2(r2[7], Sb[7], aB);
        ys[a] = ys[a] + (aA.x + aB.x) + (aA.y + aB.y) + dC * x;
    }
    __syncthreads();

    // vectorized coalesced stream-out
    for (int s = tid; s < L_SEQ / 4; s += 256) {
        const int t = s * 4;
        const float* p = ys + t + (t >> 5);
        *(float4*)(yrow + t) = make_float4(p[0], p[1], p[2], p[3]);
    }
}

// ---------------------------------------------------------------------------
// Kernel 3: gate FIR (x2) + multiply + transpose to (B, L, HID) output.
__global__ __launch_bounds__(256) void k_gate_out(const float* __restrict__ u,
                                                  const float* __restrict__ w,
                                                  float* __restrict__ out) {
    const int t0   = blockIdx.x * 64;
    const int head = blockIdx.y;
    const int b    = blockIdx.z;
    const int tid  = threadIdx.x;

    __shared__ float su[68 * 68];   // x2 u tile: 68 t rows x 64 ch (pad->68)
    __shared__ float sy[64 * 65];   // y tile: 64 ch x 64 t (pad 65)
    __shared__ float sw[64 * 3];

    const int chbase = head * 192;  // x2 channels

    for (int i = tid; i < 192; i += 256) sw[i] = w[chbase * 3 + i];

    for (int s = tid; s < 68 * 16; s += 256) {
        const int row = s >> 4, c4 = s & 15;
        const int t = t0 - 2 + row;
        float4 v = make_float4(0.f, 0.f, 0.f, 0.f);
        if (t >= 0 && t < L_SEQ)
            v = *(const float4*)(u + (size_t)(b * L_SEQ + t) * C3 + chbase + c4 * 4);
        *(float4*)(su + row * 68 + c4 * 4) = v;
    }
    for (int s = tid; s < 64 * 16; s += 256) {
        const int dch = s >> 4, c4 = s & 15;
        const float4 v = *(const float4*)(g_y + (size_t)(b * HIDN + head * HD + dch) * L_SEQ + t0 + c4 * 4);
        float* dst = sy + dch * 65 + c4 * 4;
        dst[0] = v.x; dst[1] = v.y; dst[2] = v.z; dst[3] = v.w;
    }
    __syncthreads();

    const int d = tid & 63;
    const int q = tid >> 6;
    const float w0 = sw[d * 3], w1 = sw[d * 3 + 1], w2s = 2.f * sw[d * 3 + 2];

    const float* p  = su + (q * 16) * 68 + d;
    const float* py = sy + d * 65 + q * 16;

    float a0 = p[0], a1 = p[68], a2 = p[136], a3 = p[204];
    float* orow = out + (size_t)(b * L_SEQ + t0 + q * 16) * HIDN + head * HD + d;

#pragma unroll
    for (int k = 0; k < 16; k++) {
        const float a4 = p[(k + 4) * 68];
        const float x2 = w0 * (a0 + a4) + w1 * (a1 + a3) + w2s * a2;
        orow[(size_t)k * HIDN] = py[k] * x2;     // 128B coalesced per k
        a0 = a1; a1 = a2; a2 = a3; a3 = a4;
    }
}

// ---------------------------------------------------------------------------
extern "C" void kernel_launch(void* const* d_in, const int* in_sizes, int n_in,
                              void* d_out, int out_size) {
    const float* u   = (const float*)d_in[0];
    const float* w   = (const float*)d_in[1];
    const float* lp  = (const float*)d_in[2];
    const float* res = (const float*)d_in[3];
    const float* D   = (const float*)d_in[4];
    float* out = (float*)d_out;

    const size_t SH = (size_t)(2 * PADN) * sizeof(float);  // 67584 B
    cudaFuncSetAttribute(k_scan, cudaFuncAttributeMaxDynamicSharedMemorySize, (int)SH);

    dim3 blk(256);
    k_fir_x1v<<<dim3(L_SEQ / 64, HEADS, BATCH), blk>>>(u, w);
    k_scan<<<dim3(BATCH * HIDN), blk, SH>>>(lp, res, D);
    k_gate_out<<<dim3(L_SEQ / 64, HEADS, BATCH), blk>>>(u, w, out);
}

// round 13
// speedup vs baseline: 1.1420x; 1.0109x over previous
#include <cuda_runtime.h>

// Problem constants
#define L_SEQ   8192
#define HIDN    1024
#define HEADS   16
#define HD      64
#define C3      3072
#define NSTATE  16
#define BATCH   2

// Scratch (allowed: __device__ global arrays)
__device__ float g_x1v[(size_t)BATCH * HIDN * L_SEQ];   // (B, HID, L) channel-major
__device__ float g_y  [(size_t)BATCH * HIDN * L_SEQ];   // (B, HID, L) y + D*x1v

// ---------------------------------------------------------------------------
// packed fp32x2 FMA (Blackwell)
union F2U { float2 f; unsigned long long u; };
__device__ __forceinline__ float2 ffma2(float2 a, float2 b, float2 c) {
    F2U A, B, C, D; A.f = a; B.f = b; C.f = c;
    asm("fma.rn.f32x2 %0, %1, %2, %3;" : "=l"(D.u) : "l"(A.u), "l"(B.u), "l"(C.u));
    return D.f;
}

// ---------------------------------------------------------------------------
// Kernel 1: bidirectional depthwise FIR (K=3) on x1/v channels, produce x1v.
// z[t] = w0*(u[t-2]+u[t+2]) + w1*(u[t-1]+u[t+1]) + 2*w2*u[t]
// Rolling window (1 LDS/channel/t) + smem staging so the g_x1v store is
// fully coalesced (lanes over t) instead of 32-line scattered STG.128.
__global__ __launch_bounds__(256) void k_fir_x1v(const float* __restrict__ u,
                                                 const float* __restrict__ w) {
    const int t0   = blockIdx.x * 64;
    const int head = blockIdx.y;
    const int b    = blockIdx.z;
    const int tid  = threadIdx.x;

    __shared__ float su[68 * 132];   // 68 time rows x 128 ch (pad->132)
    __shared__ float st[64 * 65];    // staging: 64 ch x 64 t (pad 65)
    __shared__ float sw[128 * 3];

    const int chbase = head * 192 + 64;   // x1 ch [0,64), v ch [64,128)

    for (int i = tid; i < 384; i += 256) sw[i] = w[chbase * 3 + i];

    for (int s = tid; s < 68 * 32; s += 256) {
        const int row = s >> 5, c4 = s & 31;
        const int t = t0 - 2 + row;
        float4 v = make_float4(0.f, 0.f, 0.f, 0.f);
        if (t >= 0 && t < L_SEQ)
            v = *(const float4*)(u + (size_t)(b * L_SEQ + t) * C3 + chbase + c4 * 4);
        *(float4*)(su + row * 132 + c4 * 4) = v;
    }
    __syncthreads();

    const int d = tid & 63;            // channel within head
    const int q = tid >> 6;            // t-quarter: t in [q*16, q*16+16)

    const float wa0 = sw[d * 3], wa1 = sw[d * 3 + 1], wa2s = 2.f * sw[d * 3 + 2];
    const float wb0 = sw[(64 + d) * 3], wb1 = sw[(64 + d) * 3 + 1],
                wb2s = 2.f * sw[(64 + d) * 3 + 2];

    const float* pa = su + (q * 16) * 132 + d;        // x1 column
    const float* pb = pa + 64;                        // v column
    float a0 = pa[0], a1 = pa[132], a2 = pa[264], a3 = pa[396];
    float b0 = pb[0], b1 = pb[132], b2 = pb[264], b3 = pb[396];

    float* srow = st + d * 65 + q * 16;

#pragma unroll
    for (int k = 0; k < 16; k++) {
        const float a4 = pa[(k + 4) * 132];
        const float b4 = pb[(k + 4) * 132];
        const float z1 = wa0 * (a0 + a4) + wa1 * (a1 + a3) + wa2s * a2;
        const float z2 = wb0 * (b0 + b4) + wb1 * (b1 + b3) + wb2s * b2;
        srow[k] = z1 * z2;            // lanes over d, stride 65: conflict-free
        a0 = a1; a1 = a2; a2 = a3; a3 = a4;
        b0 = b1; b1 = b2; b2 = b3; b3 = b4;
    }
    __syncthreads();

    // coalesced store: s -> (ch, 16B chunk of t)
    for (int s = tid; s < 64 * 16; s += 256) {
        const int ch = s >> 4, c4 = s & 15;
        const float* p = st + ch * 65 + c4 * 4;
        float4 v = make_float4(p[0], p[1], p[2], p[3]);
        *(float4*)(g_x1v + (size_t)(b * HIDN + head * HD + ch) * L_SEQ + t0 + c4 * 4) = v;
    }
}

// ---------------------------------------------------------------------------
// Kernel 2: bidirectional 16-state SSM scan per (b, channel) row.
// Combined-direction version: thread tid owns t in [tid*32, tid*32+32) for
// BOTH directions (bwd chunk index = 255-tid), so one set of Kogge-Stone
// barrier rounds serves both scans. Carry buffer aliases the y buffer.
#define PADN 8448         // 8192 + 256 pad floats
#define SCST 33           // carry row stride (floats): 32 payload + 1 pad

__global__ __launch_bounds__(256, 3) void k_scan(const float* __restrict__ lp,
                                                 const float* __restrict__ res,
                                                 const float* __restrict__ Dv) {
    extern __shared__ float sm[];
    float* xs = sm;                 // padded x1v row  (8448)
    float* ys = sm + PADN;          // padded y row    (8448)  [aliases carries]
    float* sc = ys;                 // carries 256*33 = 8448 (used before ys writes)

    const int tid = threadIdx.x;        // chunk id (fwd); bwd chunk = 255-tid
    const int bc  = blockIdx.x;         // b*HID + c
    const float* xrow = g_x1v + (size_t)bc * L_SEQ;
    float*       yrow = g_y   + (size_t)bc * L_SEQ;
    const float dC = Dv[bc & (HIDN - 1)];

    float2 p2[8], r2[8];
#pragma unroll
    for (int k = 0; k < 8; k++) {
        p2[k] = make_float2(expf(lp[2 * k]), expf(lp[2 * k + 1]));
        r2[k] = make_float2(res[2 * k], res[2 * k + 1]);
    }

    // vectorized load into padded smem (pad = t>>5)
    for (int s = tid; s < L_SEQ / 4; s += 256) {
        const float4 v = *(const float4*)(xrow + s * 4);
        const int t = s * 4;
        float* dst = xs + t + (t >> 5);
        dst[0] = v.x; dst[1] = v.y; dst[2] = v.z; dst[3] = v.w;
    }
    __syncthreads();

    const int base = 33 * tid;          // thread's padded t-range start

    // ---- pass 1: local chunk scans, both directions in one loop ----
    float2 Sf[8], Sb[8];
#pragma unroll
    for (int k = 0; k < 8; k++) { Sf[k] = make_float2(0.f, 0.f); Sb[k] = Sf[k]; }

#pragma unroll 4
    for (int i = 0; i < 32; i++) {
        const float xf = xs[base + i];
        const float xb = xs[base + 31 - i];
        const float2 f = make_float2(xf, xf);
        const float2 g = make_float2(xb, xb);
#pragma unroll
        for (int k = 0; k < 8; k++) {
            Sf[k] = ffma2(p2[k], Sf[k], f);
            Sb[k] = ffma2(p2[k], Sb[k], g);
        }
    }

    // chunk decay q = p^32 (shared by both directions)
    float2 q2[8];
#pragma unroll
    for (int k = 0; k < 8; k++) {
        float2 q = p2[k];
#pragma unroll
        for (int sq = 0; sq < 5; sq++) { q.x *= q.x; q.y *= q.y; }
        q2[k] = q;
    }

    // ---- Kogge-Stone over 256 chunk carries, both dirs per round ----
    for (int d = 1; d < 256; d <<= 1) {
#pragma unroll
        for (int k = 0; k < 8; k++) {
            sc[tid * SCST + 2 * k]          = Sf[k].x;
            sc[tid * SCST + 2 * k + 1]      = Sf[k].y;
            sc[tid * SCST + 16 + 2 * k]     = Sb[k].x;
            sc[tid * SCST + 16 + 2 * k + 1] = Sb[k].y;
        }
        __syncthreads();
        const bool af = (tid >= d);
        const bool ab = (tid + d < 256);
        float2 Pf[8], Pb[8];
        if (af) {
#pragma unroll
            for (int k = 0; k < 8; k++)
                Pf[k] = make_float2(sc[(tid - d) * SCST + 2 * k],
                                    sc[(tid - d) * SCST + 2 * k + 1]);
        }
        if (ab) {
#pragma unroll
            for (int k = 0; k < 8; k++)
                Pb[k] = make_float2(sc[(tid + d) * SCST + 16 + 2 * k],
                                    sc[(tid + d) * SCST + 16 + 2 * k + 1]);
        }
        __syncthreads();
        if (af) {
#pragma unroll
            for (int k = 0; k < 8; k++) Sf[k] = ffma2(q2[k], Pf[k], Sf[k]);
        }
        if (ab) {
#pragma unroll
            for (int k = 0; k < 8; k++) Sb[k] = ffma2(q2[k], Pb[k], Sb[k]);
        }
#pragma unroll
        for (int k = 0; k < 8; k++) { q2[k].x *= q2[k].x; q2[k].y *= q2[k].y; }
    }

    // ---- exclusive carry-in: fwd from tid-1, bwd from tid+1 ----
#pragma unroll
    for (int k = 0; k < 8; k++) {
        sc[tid * SCST + 2 * k]          = Sf[k].x;
        sc[tid * SCST + 2 * k + 1]      = Sf[k].y;
        sc[tid * SCST + 16 + 2 * k]     = Sb[k].x;
        sc[tid * SCST + 16 + 2 * k + 1] = Sb[k].y;
    }
    __syncthreads();
    if (tid > 0) {
#pragma unroll
        for (int k = 0; k < 8; k++)
            Sf[k] = make_float2(sc[(tid - 1) * SCST + 2 * k],
                                sc[(tid - 1) * SCST + 2 * k + 1]);
    } else {
#pragma unroll
        for (int k = 0; k < 8; k++) Sf[k] = make_float2(0.f, 0.f);
    }
    if (tid < 255) {
#pragma unroll
        for (int k = 0; k < 8; k++)
            Sb[k] = make_float2(sc[(tid + 1) * SCST + 16 + 2 * k],
                                sc[(tid + 1) * SCST + 16 + 2 * k + 1]);
    } else {
#pragma unroll
        for (int k = 0; k < 8; k++) Sb[k] = make_float2(0.f, 0.f);
    }
    __syncthreads();   // all carry reads done before ys (same memory) is written

    // ---- pass 2A: forward finish, write yf ----
#pragma unroll 4
    for (int i = 0; i < 32; i++) {
        const int a = base + i;
        const float x = xs[a];
        const float2 fx = make_float2(x, x);
#pragma unroll
        for (int k = 0; k < 8; k++) Sf[k] = ffma2(p2[k], Sf[k], fx);
        float2 aA = make_float2(0.f, 0.f), aB = make_float2(0.f, 0.f);
        aA = ffma2(r2[0], Sf[0], aA);  aB = ffma2(r2[1], Sf[1], aB);
        aA = ffma2(r2[2], Sf[2], aA);  aB = ffma2(r2[3], Sf[3], aB);
        aA = ffma2(r2[4], Sf[4], aA);  aB = ffma2(r2[5], Sf[5], aB);
        aA = ffma2(r2[6], Sf[6], aA);  aB = ffma2(r2[7], Sf[7], aB);
        ys[a] = (aA.x + aB.x) + (aA.y + aB.y);
    }

    // ---- pass 2B: backward finish, accumulate (same-thread addresses) ----
#pragma unroll 4
    for (int i = 0; i < 32; i++) {
        const int a = base + 31 - i;
        const float x = xs[a];
        const float2 fx = make_float2(x, x);
#pragma unroll
        for (int k = 0; k < 8; k++) Sb[k] = ffma2(p2[k], Sb[k], fx);
        float2 aA = make_float2(0.f, 0.f), aB = make_float2(0.f, 0.f);
        aA = ffma2(r2[0], Sb[0], aA);  aB = ffma2(r2[1], Sb[1], aB);
        aA = ffma2(r2[2], Sb[2], aA);  aB = ffma2(r2[3], Sb[3], aB);
        aA = ffma2(r2[4], Sb[4], aA);  aB = ffma2(r2[5], Sb[5], aB);
        aA = ffma2(r2[6], Sb[6], aA);  aB = ffma2(r2[7], Sb[7], aB);
        ys[a] = ys[a] + (aA.x + aB.x) + (aA.y + aB.y) + dC * x;
    }
    __syncthreads();

    // vectorized coalesced stream-out
    for (int s = tid; s < L_SEQ / 4; s += 256) {
        const int t = s * 4;
        const float* p = ys + t + (t >> 5);
        *(float4*)(yrow + t) = make_float4(p[0], p[1], p[2], p[3]);
    }
}

// ---------------------------------------------------------------------------
// Kernel 3: gate FIR (x2) + multiply + transpose to (B, L, HID) output.
__global__ __launch_bounds__(256) void k_gate_out(const float* __restrict__ u,
                                                  const float* __restrict__ w,
                                                  float* __restrict__ out) {
    const int t0   = blockIdx.x * 64;
    const int head = blockIdx.y;
    const int b    = blockIdx.z;
    const int tid  = threadIdx.x;

    __shared__ float su[68 * 68];   // x2 u tile: 68 t rows x 64 ch (pad->68)
    __shared__ float sy[64 * 65];   // y tile: 64 ch x 64 t (pad 65)
    __shared__ float sw[64 * 3];

    const int chbase = head * 192;  // x2 channels

    for (int i = tid; i < 192; i += 256) sw[i] = w[chbase * 3 + i];

    for (int s = tid; s < 68 * 16; s += 256) {
        const int row = s >> 4, c4 = s & 15;
        const int t = t0 - 2 + row;
        float4 v = make_float4(0.f, 0.f, 0.f, 0.f);
        if (t >= 0 && t < L_SEQ)
            v = *(const float4*)(u + (size_t)(b * L_SEQ + t) * C3 + chbase + c4 * 4);
        *(float4*)(su + row * 68 + c4 * 4) = v;
    }
    for (int s = tid; s < 64 * 16; s += 256) {
        const int dch = s >> 4, c4 = s & 15;
        const float4 v = *(const float4*)(g_y + (size_t)(b * HIDN + head * HD + dch) * L_SEQ + t0 + c4 * 4);
        float* dst = sy + dch * 65 + c4 * 4;
        dst[0] = v.x; dst[1] = v.y; dst[2] = v.z; dst[3] = v.w;
    }
    __syncthreads();

    const int d = tid & 63;
    const int q = tid >> 6;
    const float w0 = sw[d * 3], w1 = sw[d * 3 + 1], w2s = 2.f * sw[d * 3 + 2];

    const float* p  = su + (q * 16) * 68 + d;
    const float* py = sy + d * 65 + q * 16;

    float a0 = p[0], a1 = p[68], a2 = p[136], a3 = p[204];
    float* orow = out + (size_t)(b * L_SEQ + t0 + q * 16) * HIDN + head * HD + d;

#pragma unroll
    for (int k = 0; k < 16; k++) {
        const float a4 = p[(k + 4) * 68];
        const float x2 = w0 * (a0 + a4) + w1 * (a1 + a3) + w2s * a2;
        orow[(size_t)k * HIDN] = py[k] * x2;     // 128B coalesced per k
        a0 = a1; a1 = a2; a2 = a3; a3 = a4;
    }
}

// ---------------------------------------------------------------------------
extern "C" void kernel_launch(void* const* d_in, const int* in_sizes, int n_in,
                              void* d_out, int out_size) {
    const float* u   = (const float*)d_in[0];
    const float* w   = (const float*)d_in[1];
    const float* lp  = (const float*)d_in[2];
    const float* res = (const float*)d_in[3];
    const float* D   = (const float*)d_in[4];
    float* out = (float*)d_out;

    const size_t SH = (size_t)(2 * PADN) * sizeof(float);  // 67584 B
    cudaFuncSetAttribute(k_scan, cudaFuncAttributeMaxDynamicSharedMemorySize, (int)SH);

    dim3 blk(256);
    k_fir_x1v<<<dim3(L_SEQ / 64, HEADS, BATCH), blk>>>(u, w);
    k_scan<<<dim3(BATCH * HIDN), blk, SH>>>(lp, res, D);
    k_gate_out<<<dim3(L_SEQ / 64, HEADS, BATCH), blk>>>(u, w, out);
}

// round 17
// speedup vs baseline: 1.1435x; 1.0013x over previous
#include <cuda_runtime.h>

// Problem constants
#define L_SEQ   8192
#define HIDN    1024
#define HEADS   16
#define HD      64
#define C3      3072
#define NSTATE  16
#define BATCH   2

// Scratch (allowed: __device__ global arrays)
__device__ float g_x1v[(size_t)BATCH * HIDN * L_SEQ];   // (B, HID, L) channel-major
__device__ float g_y  [(size_t)BATCH * HIDN * L_SEQ];   // (B, HID, L) y + D*x1v

// ---------------------------------------------------------------------------
// packed fp32x2 FMA (Blackwell)
union F2U { float2 f; unsigned long long u; };
__device__ __forceinline__ float2 ffma2(float2 a, float2 b, float2 c) {
    F2U A, B, C, D; A.f = a; B.f = b; C.f = c;
    asm("fma.rn.f32x2 %0, %1, %2, %3;" : "=l"(D.u) : "l"(A.u), "l"(B.u), "l"(C.u));
    return D.f;
}

// ---------------------------------------------------------------------------
// Kernel 1: bidirectional depthwise FIR (K=3) on x1/v channels, produce x1v.
// z[t] = w0*(u[t-2]+u[t+2]) + w1*(u[t-1]+u[t+1]) + 2*w2*u[t]
// t-tile = 32 -> smem ~20.5KB -> ~7 blocks/SM (latency hiding), rolling window.
__global__ __launch_bounds__(256) void k_fir_x1v(const float* __restrict__ u,
                                                 const float* __restrict__ w) {
    const int t0   = blockIdx.x * 32;
    const int head = blockIdx.y;
    const int b    = blockIdx.z;
    const int tid  = threadIdx.x;

    __shared__ float su[36 * 132];   // 36 time rows x 128 ch (pad->132)
    __shared__ float sw[128 * 3];

    const int chbase = head * 192 + 64;   // x1 ch [0,64), v ch [64,128)

    for (int i = tid; i < 384; i += 256) sw[i] = w[chbase * 3 + i];

    for (int s = tid; s < 36 * 32; s += 256) {
        const int row = s >> 5, c4 = s & 31;
        const int t = t0 - 2 + row;
        float4 v = make_float4(0.f, 0.f, 0.f, 0.f);
        if (t >= 0 && t < L_SEQ)
            v = *(const float4*)(u + (size_t)(b * L_SEQ + t) * C3 + chbase + c4 * 4);
        *(float4*)(su + row * 132 + c4 * 4) = v;
    }
    __syncthreads();

    const int d = tid & 63;            // channel within head
    const int q = tid >> 6;            // t-eighth: t in [q*8, q*8+8)

    const float wa0 = sw[d * 3], wa1 = sw[d * 3 + 1], wa2s = 2.f * sw[d * 3 + 2];
    const float wb0 = sw[(64 + d) * 3], wb1 = sw[(64 + d) * 3 + 1],
                wb2s = 2.f * sw[(64 + d) * 3 + 2];

    const float* pa = su + (q * 8) * 132 + d;         // x1 column
    const float* pb = pa + 64;                        // v column
    float a0 = pa[0], a1 = pa[132], a2 = pa[264], a3 = pa[396];
    float b0 = pb[0], b1 = pb[132], b2 = pb[264], b3 = pb[396];

    float* orow = g_x1v + (size_t)(b * HIDN + head * HD + d) * L_SEQ + t0 + q * 8;

    float4 buf;
#pragma unroll
    for (int k = 0; k < 8; k++) {
        const float a4 = pa[(k + 4) * 132];
        const float b4 = pb[(k + 4) * 132];
        const float z1 = wa0 * (a0 + a4) + wa1 * (a1 + a3) + wa2s * a2;
        const float z2 = wb0 * (b0 + b4) + wb1 * (b1 + b3) + wb2s * b2;
        const float z = z1 * z2;
        if ((k & 3) == 0) buf.x = z;
        else if ((k & 3) == 1) buf.y = z;
        else if ((k & 3) == 2) buf.z = z;
        else { buf.w = z; *(float4*)(orow + (k & ~3)) = buf; }
        a0 = a1; a1 = a2; a2 = a3; a3 = a4;
        b0 = b1; b1 = b2; b2 = b3; b3 = b4;
    }
}

// ---------------------------------------------------------------------------
// Kernel 2: bidirectional 16-state SSM scan per (b, channel) row.
// Warp-shuffle Kogge-Stone (rounds 1..16 in registers, no barriers) +
// cross-warp combine via 8 smem aggregates and the closed-form decay
// p^(32*lane). Only 4 block barriers total.
#define PADN 8448         // 8192 + 256 pad floats

__global__ __launch_bounds__(256, 3) void k_scan(const float* __restrict__ lp,
                                                 const float* __restrict__ res,
                                                 const float* __restrict__ Dv) {
    extern __shared__ float sm[];
    float* xs  = sm;                // padded x1v row  (8448)
    float* ys  = sm + PADN;         // padded y row    (8448)
    float* swc = ys;                // warp-aggregate exchange (256 floats, pre-ys)

    const int tid  = threadIdx.x;       // chunk id, t in [tid*32, tid*32+32)
    const int lane = tid & 31;
    const int wrp  = tid >> 5;
    const int bc   = blockIdx.x;        // b*HID + c
    const float* xrow = g_x1v + (size_t)bc * L_SEQ;
    float*       yrow = g_y   + (size_t)bc * L_SEQ;
    const float dC = Dv[bc & (HIDN - 1)];

    float2 p2[8], r2[8];
#pragma unroll
    for (int k = 0; k < 8; k++) {
        p2[k] = make_float2(expf(lp[2 * k]), expf(lp[2 * k + 1]));
        r2[k] = make_float2(res[2 * k], res[2 * k + 1]);
    }

    // vectorized load into padded smem (pad = t>>5)
    for (int s = tid; s < L_SEQ / 4; s += 256) {
        const float4 v = *(const float4*)(xrow + s * 4);
        const int t = s * 4;
        float* dst = xs + t + (t >> 5);
        dst[0] = v.x; dst[1] = v.y; dst[2] = v.z; dst[3] = v.w;
    }
    __syncthreads();                                    // (1)

    const int base = 33 * tid;

    // ---- pass 1: local chunk scans, both directions ----
    float2 Sf[8], Sb[8];
#pragma unroll
    for (int k = 0; k < 8; k++) { Sf[k] = make_float2(0.f, 0.f); Sb[k] = Sf[k]; }

#pragma unroll 4
    for (int i = 0; i < 32; i++) {
        const float xf = xs[base + i];
        const float xb = xs[base + 31 - i];
        const float2 f = make_float2(xf, xf);
        const float2 g = make_float2(xb, xb);
#pragma unroll
        for (int k = 0; k < 8; k++) {
            Sf[k] = ffma2(p2[k], Sf[k], f);
            Sb[k] = ffma2(p2[k], Sb[k], g);
        }
    }

    // chunk decay q2 = p^32
    float2 q2[8];
#pragma unroll
    for (int k = 0; k < 8; k++) {
        float2 q = p2[k];
#pragma unroll
        for (int sq = 0; sq < 5; sq++) { q.x *= q.x; q.y *= q.y; }
        q2[k] = q;
    }

    // ---- intra-warp Kogge-Stone via shuffles (no barriers) ----
#pragma unroll
    for (int d = 1; d < 32; d <<= 1) {
#pragma unroll
        for (int k = 0; k < 8; k++) {
            const float fx = __shfl_up_sync(0xffffffffu, Sf[k].x, d);
            const float fy = __shfl_up_sync(0xffffffffu, Sf[k].y, d);
            const float bx = __shfl_down_sync(0xffffffffu, Sb[k].x, d);
            const float by = __shfl_down_sync(0xffffffffu, Sb[k].y, d);
            if (lane >= d)     Sf[k] = ffma2(q2[k], make_float2(fx, fy), Sf[k]);
            if (lane + d < 32) Sb[k] = ffma2(q2[k], make_float2(bx, by), Sb[k]);
        }
#pragma unroll
        for (int k = 0; k < 8; k++) { q2[k].x *= q2[k].x; q2[k].y *= q2[k].y; }
    }
    // q2 is now Q = p^1024 (per-warp span decay)

    // ---- publish warp aggregates ----
    if (lane == 31) {
#pragma unroll
        for (int k = 0; k < 8; k++) {
            swc[wrp * 16 + 2 * k]     = Sf[k].x;
            swc[wrp * 16 + 2 * k + 1] = Sf[k].y;
        }
    }
    if (lane == 0) {
#pragma unroll
        for (int k = 0; k < 8; k++) {
            swc[128 + wrp * 16 + 2 * k]     = Sb[k].x;
            swc[128 + wrp * 16 + 2 * k + 1] = Sb[k].y;
        }
    }
    __syncthreads();                                    // (2)

    // ---- cross-warp prefixes: Bf = sum_{w'<w} Q^{w-1-w'} Af_{w'} ----
    float2 Bf[8], Bb[8];
#pragma unroll
    for (int k = 0; k < 8; k++) { Bf[k] = make_float2(0.f, 0.f); Bb[k] = Bf[k]; }
    for (int w2 = 0; w2 < wrp; w2++) {
#pragma unroll
        for (int k = 0; k < 8; k++)
            Bf[k] = ffma2(q2[k], Bf[k],
                          make_float2(swc[w2 * 16 + 2 * k], swc[w2 * 16 + 2 * k + 1]));
    }
    for (int w2 = 7; w2 > wrp; w2--) {
#pragma unroll
        for (int k = 0; k < 8; k++)
            Bb[k] = ffma2(q2[k], Bb[k],
                          make_float2(swc[128 + w2 * 16 + 2 * k],
                                      swc[128 + w2 * 16 + 2 * k + 1]));
    }
    __syncthreads();                                    // (3) swc reads done; ys free

    // ---- exclusive carry-in: within-warp prev (shfl) + decayed cross-warp ----
    const float ef32 = 32.f * (float)lane;
    const float eb32 = 32.f * (float)(31 - lane);
#pragma unroll
    for (int k = 0; k < 8; k++) {
        const float l0 = lp[2 * k], l1 = lp[2 * k + 1];
        const float2 eF = make_float2(expf(l0 * ef32), expf(l1 * ef32)); // p^(32*lane)
        const float2 eB = make_float2(expf(l0 * eb32), expf(l1 * eb32)); // p^(32*(31-lane))
        const float px = __shfl_up_sync(0xffffffffu, Sf[k].x, 1);
        const float py = __shfl_up_sync(0xffffffffu, Sf[k].y, 1);
        const float nx = __shfl_down_sync(0xffffffffu, Sb[k].x, 1);
        const float ny = __shfl_down_sync(0xffffffffu, Sb[k].y, 1);
        const float2 pv = (lane > 0)  ? make_float2(px, py) : make_float2(0.f, 0.f);
        const float2 nv = (lane < 31) ? make_float2(nx, ny) : make_float2(0.f, 0.f);
        Sf[k] = ffma2(eF, Bf[k], pv);
        Sb[k] = ffma2(eB, Bb[k], nv);
    }

    // ---- pass 2A: forward finish, write yf ----
#pragma unroll 4
    for (int i = 0; i < 32; i++) {
        const int a = base + i;
        const float x = xs[a];
        const float2 fx = make_float2(x, x);
#pragma unroll
        for (int k = 0; k < 8; k++) Sf[k] = ffma2(p2[k], Sf[k], fx);
        float2 aA = make_float2(0.f, 0.f), aB = make_float2(0.f, 0.f);
        aA = ffma2(r2[0], Sf[0], aA);  aB = ffma2(r2[1], Sf[1], aB);
        aA = ffma2(r2[2], Sf[2], aA);  aB = ffma2(r2[3], Sf[3], aB);
        aA = ffma2(r2[4], Sf[4], aA);  aB = ffma2(r2[5], Sf[5], aB);
        aA = ffma2(r2[6], Sf[6], aA);  aB = ffma2(r2[7], Sf[7], aB);
        ys[a] = (aA.x + aB.x) + (aA.y + aB.y);
    }

    // ---- pass 2B: backward finish, accumulate (same-thread addresses) ----
#pragma unroll 4
    for (int i = 0; i < 32; i++) {
        const int a = base + 31 - i;
        const float x = xs[a];
        const float2 fx = make_float2(x, x);
#pragma unroll
        for (int k = 0; k < 8; k++) Sb[k] = ffma2(p2[k], Sb[k], fx);
        float2 aA = make_float2(0.f, 0.f), aB = make_float2(0.f, 0.f);
        aA = ffma2(r2[0], Sb[0], aA);  aB = ffma2(r2[1], Sb[1], aB);
        aA = ffma2(r2[2], Sb[2], aA);  aB = ffma2(r2[3], Sb[3], aB);
        aA = ffma2(r2[4], Sb[4], aA);  aB = ffma2(r2[5], Sb[5], aB);
        aA = ffma2(r2[6], Sb[6], aA);  aB = ffma2(r2[7], Sb[7], aB);
        ys[a] = ys[a] + (aA.x + aB.x) + (aA.y + aB.y) + dC * x;
    }
    __syncthreads();                                    // (4)

    // vectorized coalesced stream-out
    for (int s = tid; s < L_SEQ / 4; s += 256) {
        const int t = s * 4;
        const float* p = ys + t + (t >> 5);
        *(float4*)(yrow + t) = make_float4(p[0], p[1], p[2], p[3]);
    }
}

// ---------------------------------------------------------------------------
// Kernel 3: gate FIR (x2) + multiply + transpose to (B, L, HID) output.
// t-tile = 32 -> smem ~19KB -> 8 blocks/SM.
__global__ __launch_bounds__(256) void k_gate_out(const float* __restrict__ u,
                                                  const float* __restrict__ w,
                                                  float* __restrict__ out) {
    const int t0   = blockIdx.x * 32;
    const int head = blockIdx.y;
    const int b    = blockIdx.z;
    const int tid  = threadIdx.x;

    __shared__ float su[36 * 68];   // x2 u tile: 36 t rows x 64 ch (pad->68)
    __shared__ float sy[64 * 33];   // y tile: 64 ch x 32 t (pad 33)
    __shared__ float sw[64 * 3];

    const int chbase = head * 192;  // x2 channels

    for (int i = tid; i < 192; i += 256) sw[i] = w[chbase * 3 + i];

    for (int s = tid; s < 36 * 16; s += 256) {
        const int row = s >> 4, c4 = s & 15;
        const int t = t0 - 2 + row;
        float4 v = make_float4(0.f, 0.f, 0.f, 0.f);
        if (t >= 0 && t < L_SEQ)
            v = *(const float4*)(u + (size_t)(b * L_SEQ + t) * C3 + chbase + c4 * 4);
        *(float4*)(su + row * 68 + c4 * 4) = v;
    }
    for (int s = tid; s < 64 * 8; s += 256) {
        const int dch = s >> 3, c4 = s & 7;
        const float4 v = *(const float4*)(g_y + (size_t)(b * HIDN + head * HD + dch) * L_SEQ + t0 + c4 * 4);
        float* dst = sy + dch * 33 + c4 * 4;
        dst[0] = v.x; dst[1] = v.y; dst[2] = v.z; dst[3] = v.w;
    }
    __syncthreads();

    const int d = tid & 63;
    const int q = tid >> 6;
    const float w0 = sw[d * 3], w1 = sw[d * 3 + 1], w2s = 2.f * sw[d * 3 + 2];

    const float* p  = su + (q * 8) * 68 + d;
    const float* py = sy + d * 33 + q * 8;

    float a0 = p[0], a1 = p[68], a2 = p[136], a3 = p[204];
    float* orow = out + (size_t)(b * L_SEQ + t0 + q * 8) * HIDN + head * HD + d;

#pragma unroll
    for (int k = 0; k < 8; k++) {
        const float a4 = p[(k + 4) * 68];
        const float x2 = w0 * (a0 + a4) + w1 * (a1 + a3) + w2s * a2;
        orow[(size_t)k * HIDN] = py[k] * x2;     // 128B coalesced per k
        a0 = a1; a1 = a2; a2 = a3; a3 = a4;
    }
}

// ---------------------------------------------------------------------------
extern "C" void kernel_launch(void* const* d_in, const int* in_sizes, int n_in,
                              void* d_out, int out_size) {
    const float* u   = (const float*)d_in[0];
    const float* w   = (const float*)d_in[1];
    const float* lp  = (const float*)d_in[2];
    const float* res = (const float*)d_in[3];
    const float* D   = (const float*)d_in[4];
    float* out = (float*)d_out;

    const size_t SH = (size_t)(2 * PADN) * sizeof(float);  // 67584 B
    cudaFuncSetAttribute(k_scan, cudaFuncAttributeMaxDynamicSharedMemorySize, (int)SH);

    dim3 blk(256);
    k_fir_x1v<<<dim3(L_SEQ / 32, HEADS, BATCH), blk>>>(u, w);
    k_scan<<<dim3(BATCH * HIDN), blk, SH>>>(lp, res, D);
    k_gate_out<<<dim3(L_SEQ / 32, HEADS, BATCH), blk>>>(u, w, out);
}